// round 10
// baseline (speedup 1.0000x reference)
#include <cuda_runtime.h>
#include <cstdint>

#define BB 4
#define SS 4096
#define WW 512
#define EE 64

// Scratch for projected Q, K, V. Values are stored as tf32-rounded fp32 bits
// (low 13 mantissa bits zero); Q is additionally pre-scaled by qscale.
__device__ float g_Q[BB * SS * EE];
__device__ float g_K[BB * SS * EE];
__device__ float g_V[BB * SS * EE];

__device__ __forceinline__ float fast_exp2(float x) {
    float y;
    asm("ex2.approx.ftz.f32 %0, %1;" : "=f"(y) : "f"(x));
    return y;
}

__device__ __forceinline__ uint32_t f2tf(float f) {
    uint32_t r;
    asm("cvt.rna.tf32.f32 %0, %1;" : "=r"(r) : "f"(f));
    return r;
}

// D += A x B  (m16n8k8, tf32 inputs as b32 regs, f32 accum)
__device__ __forceinline__ void mma_tf32(float* d, const uint32_t* a,
                                         const uint32_t* b) {
    asm volatile(
        "mma.sync.aligned.m16n8k8.row.col.f32.tf32.tf32.f32 "
        "{%0,%1,%2,%3}, {%4,%5,%6,%7}, {%8,%9}, {%0,%1,%2,%3};"
        : "+f"(d[0]), "+f"(d[1]), "+f"(d[2]), "+f"(d[3])
        : "r"(a[0]), "r"(a[1]), "r"(a[2]), "r"(a[3]), "r"(b[0]), "r"(b[1]));
}

__device__ __forceinline__ uint32_t smem_u32(const void* p) {
    uint32_t a;
    asm("{ .reg .u64 t; cvta.to.shared.u64 t, %1; cvt.u32.u64 %0, t; }"
        : "=r"(a) : "l"(p));
    return a;
}

__device__ __forceinline__ void cp16(uint32_t dst, const void* src) {
    asm volatile("cp.async.cg.shared.global [%0], [%1], 16;"
                 :: "r"(dst), "l"(src));
}
#define CP_COMMIT() asm volatile("cp.async.commit_group;" ::: "memory")

#define QSCALE (0.125f * 1.4426950408889634f)

// ---------------------------------------------------------------------------
// Kernel 1: QKV projection via tf32 mma, 2-term split (x = hi + lo) for
// near-fp32 accuracy over the 512-deep reduction.
// grid = (16384/128, 3), block = 256 (8 warps; warp w owns rows 16w..16w+15).
// Outputs tf32-rounded bits; Q pre-scaled by QSCALE.
// ---------------------------------------------------------------------------
#define LDX 36
#define LDW 72

__global__ __launch_bounds__(256) void qkv_proj_mma(
    const float* __restrict__ x,
    const float* __restrict__ Wq, const float* __restrict__ bq,
    const float* __restrict__ Wk, const float* __restrict__ bk,
    const float* __restrict__ Wv, const float* __restrict__ bv)
{
    const int mat = blockIdx.y;
    const float* Wm = (mat == 0) ? Wq : (mat == 1) ? Wk : Wv;
    const float* bm = (mat == 0) ? bq : (mat == 1) ? bk : bv;
    float* out = (mat == 0) ? g_Q : (mat == 1) ? g_K : g_V;

    const int row0 = blockIdx.x * 128;

    __shared__ float xh[128 * LDX];
    __shared__ float xl[128 * LDX];
    __shared__ float ws[32 * LDW];

    const int tid = threadIdx.x;
    const int w = tid >> 5;
    const int lane = tid & 31;
    const int gid = lane >> 2;
    const int tig = lane & 3;

    float o[8][4];
#pragma unroll
    for (int j = 0; j < 8; j++)
#pragma unroll
        for (int i = 0; i < 4; i++) o[j][i] = 0.0f;

    for (int k0 = 0; k0 < WW; k0 += 32) {
        __syncthreads();
        // x chunk 128 rows x 32 k: hi/lo split at store
#pragma unroll
        for (int it = 0; it < 4; it++) {
            int i = tid + it * 256;
            int row = i >> 3;
            int c4 = (i & 7) * 4;
            float4 v = *(const float4*)&x[(size_t)(row0 + row) * WW + k0 + c4];
            float h0 = __uint_as_float(f2tf(v.x));
            float h1 = __uint_as_float(f2tf(v.y));
            float h2 = __uint_as_float(f2tf(v.z));
            float h3 = __uint_as_float(f2tf(v.w));
            *(float4*)&xh[row * LDX + c4] = make_float4(h0, h1, h2, h3);
            float l0 = __uint_as_float(f2tf(v.x - h0));
            float l1 = __uint_as_float(f2tf(v.y - h1));
            float l2 = __uint_as_float(f2tf(v.z - h2));
            float l3 = __uint_as_float(f2tf(v.w - h3));
            *(float4*)&xl[row * LDX + c4] = make_float4(l0, l1, l2, l3);
        }
        // W chunk 32 k x 64 n (single tf32 rounding)
#pragma unroll
        for (int it = 0; it < 2; it++) {
            int i = tid + it * 256;
            int k = i >> 4;
            int n4 = (i & 15) * 4;
            float4 v = *(const float4*)&Wm[(size_t)(k0 + k) * EE + n4];
            *(float4*)&ws[k * LDW + n4] = make_float4(
                __uint_as_float(f2tf(v.x)), __uint_as_float(f2tf(v.y)),
                __uint_as_float(f2tf(v.z)), __uint_as_float(f2tf(v.w)));
        }
        __syncthreads();

#pragma unroll
        for (int t = 0; t < 4; t++) {
            uint32_t ah[4], al[4];
            const int base0 = (16 * w + gid) * LDX + 8 * t + tig;
            const int base1 = base0 + 8 * LDX;
            ah[0] = __float_as_uint(xh[base0]);
            ah[1] = __float_as_uint(xh[base1]);
            ah[2] = __float_as_uint(xh[base0 + 4]);
            ah[3] = __float_as_uint(xh[base1 + 4]);
            al[0] = __float_as_uint(xl[base0]);
            al[1] = __float_as_uint(xl[base1]);
            al[2] = __float_as_uint(xl[base0 + 4]);
            al[3] = __float_as_uint(xl[base1 + 4]);
#pragma unroll
            for (int j = 0; j < 8; j++) {
                const uint32_t* wb =
                    (const uint32_t*)&ws[(8 * t + tig) * LDW + 8 * j + gid];
                uint32_t bfr[2];
                bfr[0] = wb[0];
                bfr[1] = wb[4 * LDW];
                mma_tf32(o[j], ah, bfr);
                mma_tf32(o[j], al, bfr);
            }
        }
    }

    // epilogue: bias, optional QSCALE, round to tf32 bits, store
    const float scale = (mat == 0) ? QSCALE : 1.0f;
    const int row = row0 + 16 * w + gid;
#pragma unroll
    for (int j = 0; j < 8; j++) {
        int c = 8 * j + 2 * tig;
        float b0 = bm[c], b1 = bm[c + 1];
        uint2 u0 = make_uint2(f2tf((o[j][0] + b0) * scale),
                              f2tf((o[j][1] + b1) * scale));
        *(uint2*)&out[(size_t)row * EE + c] = u0;
        uint2 u1 = make_uint2(f2tf((o[j][2] + b0) * scale),
                              f2tf((o[j][3] + b1) * scale));
        *(uint2*)&out[(size_t)(row + 8) * EE + c] = u1;
    }
}

// ---------------------------------------------------------------------------
// Kernel 2: flash attention via mma.sync tf32 (m16n8k8).
// grid = (4096/128, 4), block = 256 (8 warps). Warp w owns query rows
// 16w..16w+15. Loop over 32 key tiles of 128, K/V double-buffered via
// cp.async (inputs are pre-converted tf32 bits -> no per-tile cvt).
// QK uses t-outer / j-inner for 16-way HMMA ILP.
// Strides: K 68, V 72, P 132 -> conflict-free fragment loads.
// ---------------------------------------------------------------------------
#define LDK 68
#define LDV 72
#define LDP 132
#define KS_FLOATS (128 * LDK)
#define VS_FLOATS (128 * LDV)
#define SMEM_ATTN ((2 * KS_FLOATS + 2 * VS_FLOATS + 128 * LDP) * 4)  // 210944

__global__ __launch_bounds__(256, 1) void attn_mma_kernel(float* __restrict__ out)
{
    extern __shared__ float smf[];
    float* Ps = smf + 2 * KS_FLOATS + 2 * VS_FLOATS;
    const uint32_t sb = smem_u32(smf);

    const int b = blockIdx.y;
    const int q0 = blockIdx.x * 128;
    const int tid = threadIdx.x;
    const int w = tid >> 5;
    const int lane = tid & 31;
    const int gid = lane >> 2;
    const int tig = lane & 3;

    const float* Qg = g_Q + ((size_t)b * SS + q0) * EE;
    const float* Kg = g_K + (size_t)b * SS * EE;
    const float* Vg = g_V + (size_t)b * SS * EE;

    // Q fragments: already tf32 bits, pre-scaled
    uint32_t qf[8][4];
    {
        const float* Qr0 = Qg + (size_t)(16 * w + gid) * EE;
        const float* Qr1 = Qr0 + 8 * EE;
#pragma unroll
        for (int t = 0; t < 8; t++) {
            qf[t][0] = __float_as_uint(Qr0[8 * t + tig]);
            qf[t][1] = __float_as_uint(Qr1[8 * t + tig]);
            qf[t][2] = __float_as_uint(Qr0[8 * t + tig + 4]);
            qf[t][3] = __float_as_uint(Qr1[8 * t + tig + 4]);
        }
    }

    float o[8][4];
#pragma unroll
    for (int j = 0; j < 8; j++)
#pragma unroll
        for (int i = 0; i < 4; i++) o[j][i] = 0.0f;
    float lsum0 = 0.0f, lsum1 = 0.0f;

    // async tile loader: stage s gets tile kt (16B copies, no conversion)
#define ISSUE_TILE(KT, S)                                                       \
    {                                                                           \
        const float* Kt = Kg + (size_t)((KT) * 128) * EE;                       \
        const float* Vt = Vg + (size_t)((KT) * 128) * EE;                       \
        const uint32_t kb4 = sb + (uint32_t)((S) * KS_FLOATS) * 4u;             \
        const uint32_t vb4 = sb + (uint32_t)(2 * KS_FLOATS + (S) * VS_FLOATS) * 4u; \
        _Pragma("unroll")                                                       \
        for (int it = 0; it < 8; it++) {                                        \
            int i = tid + it * 256;                                             \
            int row = i >> 4;                                                   \
            int c4 = (i & 15) * 4;                                              \
            cp16(kb4 + (uint32_t)(row * LDK + c4) * 4u, Kt + (size_t)row * EE + c4); \
            cp16(vb4 + (uint32_t)(row * LDV + c4) * 4u, Vt + (size_t)row * EE + c4); \
        }                                                                       \
    }

    ISSUE_TILE(0, 0);
    CP_COMMIT();

    for (int kt = 0; kt < 32; kt++) {
        const int cur = kt & 1;
        if (kt < 31) {
            ISSUE_TILE(kt + 1, cur ^ 1);
            CP_COMMIT();
            asm volatile("cp.async.wait_group 1;" ::: "memory");
        } else {
            asm volatile("cp.async.wait_group 0;" ::: "memory");
        }
        __syncthreads();

        const float* Kc = smf + cur * KS_FLOATS;
        const float* Vc = smf + 2 * KS_FLOATS + cur * VS_FLOATS;

        // --- QK^T: t outer (k-steps), j inner (16 independent accumulators) ---
        float s[16][4];
#pragma unroll
        for (int j = 0; j < 16; j++)
            s[j][0] = s[j][1] = s[j][2] = s[j][3] = 0.0f;
#pragma unroll
        for (int t = 0; t < 8; t++) {
#pragma unroll
            for (int j = 0; j < 16; j++) {
                const uint32_t* kb =
                    (const uint32_t*)&Kc[(8 * j + gid) * LDK + 8 * t + tig];
                uint32_t bfr[2];
                bfr[0] = kb[0];
                bfr[1] = kb[4];
                mma_tf32(s[j], qf[t], bfr);
            }
        }

        // --- softmax (no max subtraction; logits bounded), write P ---
        {
            float* p0 = &Ps[(16 * w + gid) * LDP + 2 * tig];
            float* p1 = p0 + 8 * LDP;
#pragma unroll
            for (int j = 0; j < 16; j++) {
                float e0 = fast_exp2(s[j][0]);
                float e1 = fast_exp2(s[j][1]);
                float e2 = fast_exp2(s[j][2]);
                float e3 = fast_exp2(s[j][3]);
                lsum0 += e0 + e1;
                lsum1 += e2 + e3;
                uint2 u0 = make_uint2(f2tf(e0), f2tf(e1));
                uint2 u1 = make_uint2(f2tf(e2), f2tf(e3));
                *(uint2*)&p0[8 * j] = u0;
                *(uint2*)&p1[8 * j] = u1;
            }
        }
        __syncwarp();  // P round-trip is intra-warp

        // --- PV: O += P x V (t outer, 8 independent j) ---
        {
            const uint32_t* pa = (const uint32_t*)&Ps[(16 * w + gid) * LDP + tig];
            const uint32_t* vb = (const uint32_t*)&Vc[tig * LDV + gid];
#pragma unroll
            for (int t = 0; t < 16; t++) {
                uint32_t afr[4];
                afr[0] = pa[8 * t];
                afr[1] = pa[8 * t + 8 * LDP];
                afr[2] = pa[8 * t + 4];
                afr[3] = pa[8 * t + 8 * LDP + 4];
                const uint32_t* vbt = vb + 8 * t * LDV;
#pragma unroll
                for (int j = 0; j < 8; j++) {
                    uint32_t bfr[2];
                    bfr[0] = vbt[8 * j];
                    bfr[1] = vbt[4 * LDV + 8 * j];
                    mma_tf32(o[j], afr, bfr);
                }
            }
        }
        __syncthreads();
    }
#undef ISSUE_TILE

    // --- reduce l across the quad ---
    lsum0 += __shfl_xor_sync(0xffffffffu, lsum0, 1);
    lsum0 += __shfl_xor_sync(0xffffffffu, lsum0, 2);
    lsum1 += __shfl_xor_sync(0xffffffffu, lsum1, 1);
    lsum1 += __shfl_xor_sync(0xffffffffu, lsum1, 2);
    const float inv0 = 1.0f / lsum0;
    const float inv1 = 1.0f / lsum1;

    // --- epilogue ---
    float* O0 = out + ((size_t)b * SS + q0 + 16 * w + gid) * EE + 2 * tig;
    float* O1 = O0 + 8 * EE;
#pragma unroll
    for (int j = 0; j < 8; j++) {
        float2 v0 = make_float2(o[j][0] * inv0, o[j][1] * inv0);
        float2 v1 = make_float2(o[j][2] * inv1, o[j][3] * inv1);
        *(float2*)&O0[8 * j] = v0;
        *(float2*)&O1[8 * j] = v1;
    }
}

// ---------------------------------------------------------------------------

extern "C" void kernel_launch(void* const* d_in, const int* in_sizes, int n_in,
                              void* d_out, int out_size)
{
    const float* x  = (const float*)d_in[0];
    const float* Wq = (const float*)d_in[1];
    const float* bq = (const float*)d_in[2];
    const float* Wk = (const float*)d_in[3];
    const float* bk = (const float*)d_in[4];
    const float* Wv = (const float*)d_in[5];
    const float* bv = (const float*)d_in[6];
    float* out = (float*)d_out;

    cudaFuncSetAttribute(attn_mma_kernel, cudaFuncAttributeMaxDynamicSharedMemorySize,
                         (int)SMEM_ATTN);

    dim3 pgrid(BB * SS / 128, 3);
    qkv_proj_mma<<<pgrid, 256>>>(x, Wq, bq, Wk, bk, Wv, bv);

    dim3 agrid(SS / 128, BB);
    attn_mma_kernel<<<agrid, 256, SMEM_ATTN>>>(out);
}

// round 11
// speedup vs baseline: 1.2413x; 1.2413x over previous
#include <cuda_runtime.h>
#include <cuda_fp16.h>
#include <cstdint>

#define BB 4
#define SS 4096
#define WW 512
#define EE 64

// Scratch: Q,K as tf32-rounded fp32 bits (Q pre-scaled); V as fp16 TRANSPOSED [b][d][s].
__device__ float  g_Q[BB * SS * EE];
__device__ float  g_K[BB * SS * EE];
__device__ __half g_Vt[BB * EE * SS];

__device__ __forceinline__ float fast_exp2(float x) {
    float y;
    asm("ex2.approx.ftz.f32 %0, %1;" : "=f"(y) : "f"(x));
    return y;
}

__device__ __forceinline__ uint32_t f2tf(float f) {
    uint32_t r;
    asm("cvt.rna.tf32.f32 %0, %1;" : "=r"(r) : "f"(f));
    return r;
}

// D += A x B  (m16n8k8, tf32)
__device__ __forceinline__ void mma_tf32(float* d, const uint32_t* a,
                                         const uint32_t* b) {
    asm volatile(
        "mma.sync.aligned.m16n8k8.row.col.f32.tf32.tf32.f32 "
        "{%0,%1,%2,%3}, {%4,%5,%6,%7}, {%8,%9}, {%0,%1,%2,%3};"
        : "+f"(d[0]), "+f"(d[1]), "+f"(d[2]), "+f"(d[3])
        : "r"(a[0]), "r"(a[1]), "r"(a[2]), "r"(a[3]), "r"(b[0]), "r"(b[1]));
}

// D += A x B  (m16n8k16, fp16 in, fp32 accum)
__device__ __forceinline__ void mma_f16(float* d, const uint32_t* a,
                                        const uint32_t* b) {
    asm volatile(
        "mma.sync.aligned.m16n8k16.row.col.f32.f16.f16.f32 "
        "{%0,%1,%2,%3}, {%4,%5,%6,%7}, {%8,%9}, {%0,%1,%2,%3};"
        : "+f"(d[0]), "+f"(d[1]), "+f"(d[2]), "+f"(d[3])
        : "r"(a[0]), "r"(a[1]), "r"(a[2]), "r"(a[3]), "r"(b[0]), "r"(b[1]));
}

__device__ __forceinline__ uint32_t smem_u32(const void* p) {
    uint32_t a;
    asm("{ .reg .u64 t; cvta.to.shared.u64 t, %1; cvt.u32.u64 %0, t; }"
        : "=r"(a) : "l"(p));
    return a;
}

__device__ __forceinline__ void cp16(uint32_t dst, const void* src) {
    asm volatile("cp.async.cg.shared.global [%0], [%1], 16;"
                 :: "r"(dst), "l"(src));
}
#define CP_COMMIT() asm volatile("cp.async.commit_group;" ::: "memory")

#define QSCALE (0.125f * 1.4426950408889634f)

// ---------------------------------------------------------------------------
// Kernel 1: QKV projection via tf32 mma, 2-term split (x = hi + lo).
// Q/K: tf32 bits to g_Q/g_K (Q pre-scaled). V: fp16, transposed to g_Vt[d][s].
// ---------------------------------------------------------------------------
#define LDX 36
#define LDW 72

__global__ __launch_bounds__(256) void qkv_proj_mma(
    const float* __restrict__ x,
    const float* __restrict__ Wq, const float* __restrict__ bq,
    const float* __restrict__ Wk, const float* __restrict__ bk,
    const float* __restrict__ Wv, const float* __restrict__ bv)
{
    const int mat = blockIdx.y;
    const float* Wm = (mat == 0) ? Wq : (mat == 1) ? Wk : Wv;
    const float* bm = (mat == 0) ? bq : (mat == 1) ? bk : bv;

    const int row0 = blockIdx.x * 128;

    __shared__ float xh[128 * LDX];
    __shared__ float xl[128 * LDX];
    __shared__ float ws[32 * LDW];

    const int tid = threadIdx.x;
    const int w = tid >> 5;
    const int lane = tid & 31;
    const int gid = lane >> 2;
    const int tig = lane & 3;

    float o[8][4];
#pragma unroll
    for (int j = 0; j < 8; j++)
#pragma unroll
        for (int i = 0; i < 4; i++) o[j][i] = 0.0f;

    for (int k0 = 0; k0 < WW; k0 += 32) {
        __syncthreads();
#pragma unroll
        for (int it = 0; it < 4; it++) {
            int i = tid + it * 256;
            int row = i >> 3;
            int c4 = (i & 7) * 4;
            float4 v = *(const float4*)&x[(size_t)(row0 + row) * WW + k0 + c4];
            float h0 = __uint_as_float(f2tf(v.x));
            float h1 = __uint_as_float(f2tf(v.y));
            float h2 = __uint_as_float(f2tf(v.z));
            float h3 = __uint_as_float(f2tf(v.w));
            *(float4*)&xh[row * LDX + c4] = make_float4(h0, h1, h2, h3);
            float l0 = __uint_as_float(f2tf(v.x - h0));
            float l1 = __uint_as_float(f2tf(v.y - h1));
            float l2 = __uint_as_float(f2tf(v.z - h2));
            float l3 = __uint_as_float(f2tf(v.w - h3));
            *(float4*)&xl[row * LDX + c4] = make_float4(l0, l1, l2, l3);
        }
#pragma unroll
        for (int it = 0; it < 2; it++) {
            int i = tid + it * 256;
            int k = i >> 4;
            int n4 = (i & 15) * 4;
            float4 v = *(const float4*)&Wm[(size_t)(k0 + k) * EE + n4];
            *(float4*)&ws[k * LDW + n4] = make_float4(
                __uint_as_float(f2tf(v.x)), __uint_as_float(f2tf(v.y)),
                __uint_as_float(f2tf(v.z)), __uint_as_float(f2tf(v.w)));
        }
        __syncthreads();

#pragma unroll
        for (int t = 0; t < 4; t++) {
            uint32_t ah[4], al[4];
            const int base0 = (16 * w + gid) * LDX + 8 * t + tig;
            const int base1 = base0 + 8 * LDX;
            ah[0] = __float_as_uint(xh[base0]);
            ah[1] = __float_as_uint(xh[base1]);
            ah[2] = __float_as_uint(xh[base0 + 4]);
            ah[3] = __float_as_uint(xh[base1 + 4]);
            al[0] = __float_as_uint(xl[base0]);
            al[1] = __float_as_uint(xl[base1]);
            al[2] = __float_as_uint(xl[base0 + 4]);
            al[3] = __float_as_uint(xl[base1 + 4]);
#pragma unroll
            for (int j = 0; j < 8; j++) {
                const uint32_t* wb =
                    (const uint32_t*)&ws[(8 * t + tig) * LDW + 8 * j + gid];
                uint32_t bfr[2];
                bfr[0] = wb[0];
                bfr[1] = wb[4 * LDW];
                mma_tf32(o[j], ah, bfr);
                mma_tf32(o[j], al, bfr);
            }
        }
    }

    const int row = row0 + 16 * w + gid;
    if (mat == 2) {
        // V: fp16, transposed [b][d][s]
        const int bidx = row >> 12;
        const int sr = row & 4095;
#pragma unroll
        for (int j = 0; j < 8; j++) {
            int c = 8 * j + 2 * tig;
            float b0 = bm[c], b1 = bm[c + 1];
            __half* base0 = g_Vt + ((size_t)bidx * EE + c) * SS;
            __half* base1 = g_Vt + ((size_t)bidx * EE + c + 1) * SS;
            base0[sr]     = __float2half(o[j][0] + b0);
            base1[sr]     = __float2half(o[j][1] + b1);
            base0[sr + 8] = __float2half(o[j][2] + b0);
            base1[sr + 8] = __float2half(o[j][3] + b1);
        }
    } else {
        float* out = (mat == 0) ? g_Q : g_K;
        const float scale = (mat == 0) ? QSCALE : 1.0f;
#pragma unroll
        for (int j = 0; j < 8; j++) {
            int c = 8 * j + 2 * tig;
            float b0 = bm[c], b1 = bm[c + 1];
            uint2 u0 = make_uint2(f2tf((o[j][0] + b0) * scale),
                                  f2tf((o[j][1] + b1) * scale));
            *(uint2*)&out[(size_t)row * EE + c] = u0;
            uint2 u1 = make_uint2(f2tf((o[j][2] + b0) * scale),
                                  f2tf((o[j][3] + b1) * scale));
            *(uint2*)&out[(size_t)(row + 8) * EE + c] = u1;
        }
    }
}

// ---------------------------------------------------------------------------
// Kernel 2: flash attention. 512 threads (16 warps), 128 queries/CTA.
// Warp w: query group g=w>>1 (rows 16g..16g+15), key half h=w&1.
// QK: tf32 m16n8k8 over 64-key half (8 j x 8 t). PV: fp16 m16n8k16
// (4 t x 8 j). o,lsum per warp over its key half; merged at the end.
// K double-buffered f32 (stride 68), V double-buffered fp16 [d][key]
// (stride 136 halves), P fp16 (stride 136 halves). All fragment loads
// bank-conflict-free.
// ---------------------------------------------------------------------------
#define LDK 68
#define LDVH 136
#define LDPH 136
#define KSTAGE (128 * LDK * 4)          // 34816 B
#define VSTAGE (64 * LDVH * 2)          // 17408 B
#define OFF_K 0u
#define OFF_V (2u * KSTAGE)             // 69632
#define OFF_P (OFF_V + 2u * VSTAGE)     // 104448
#define OFF_LR (OFF_P + 128u * LDPH * 2u)  // 139264
#define SMEM_ATTN (OFF_LR + 1024u)      // 140288 B

__global__ __launch_bounds__(512, 1) void attn_mma_kernel(float* __restrict__ out)
{
    extern __shared__ char smem[];
    const uint32_t sb = smem_u32(smem);

    const int b = blockIdx.y;
    const int q0 = blockIdx.x * 128;
    const int tid = threadIdx.x;
    const int w = tid >> 5;
    const int g = w >> 1;
    const int h = w & 1;
    const int lane = tid & 31;
    const int gid = lane >> 2;
    const int tig = lane & 3;

    const float*  Qg = g_Q + ((size_t)b * SS + q0) * EE;
    const float*  Kg = g_K + (size_t)b * SS * EE;
    const __half* Vg = g_Vt + (size_t)b * EE * SS;

    // Q fragments (tf32 bits, pre-scaled), rows 16g+gid / +8
    uint32_t qf[8][4];
    {
        const float* Qr0 = Qg + (size_t)(16 * g + gid) * EE;
        const float* Qr1 = Qr0 + 8 * EE;
#pragma unroll
        for (int t = 0; t < 8; t++) {
            qf[t][0] = __float_as_uint(Qr0[8 * t + tig]);
            qf[t][1] = __float_as_uint(Qr1[8 * t + tig]);
            qf[t][2] = __float_as_uint(Qr0[8 * t + tig + 4]);
            qf[t][3] = __float_as_uint(Qr1[8 * t + tig + 4]);
        }
    }

    float o[8][4];
#pragma unroll
    for (int j = 0; j < 8; j++)
#pragma unroll
        for (int i = 0; i < 4; i++) o[j][i] = 0.0f;
    float lsum0 = 0.0f, lsum1 = 0.0f;

    // tile loader: K 128x64 f32 (2048 cp16), V 64x128 half (1024 cp16)
#define ISSUE_TILE(KT, S)                                                        \
    {                                                                            \
        const float* Kt = Kg + (size_t)((KT) * 128) * EE;                        \
        const uint32_t kb4 = sb + OFF_K + (uint32_t)(S) * KSTAGE;                \
        _Pragma("unroll")                                                        \
        for (int it = 0; it < 4; it++) {                                         \
            int i = tid + it * 512;                                              \
            int row = i >> 4;                                                    \
            int c4 = (i & 15) * 4;                                               \
            cp16(kb4 + (uint32_t)(row * LDK + c4) * 4u,                          \
                 Kt + (size_t)row * EE + c4);                                    \
        }                                                                        \
        const uint32_t vb2 = sb + OFF_V + (uint32_t)(S) * VSTAGE;                \
        _Pragma("unroll")                                                        \
        for (int it = 0; it < 2; it++) {                                         \
            int i = tid + it * 512;                                              \
            int row = i >> 4;                                                    \
            int c8 = (i & 15) * 8;                                               \
            cp16(vb2 + (uint32_t)(row * LDVH + c8) * 2u,                         \
                 Vg + (size_t)row * SS + (KT) * 128 + c8);                       \
        }                                                                        \
    }

    ISSUE_TILE(0, 0);
    CP_COMMIT();

    for (int kt = 0; kt < 32; kt++) {
        const int cur = kt & 1;
        if (kt < 31) {
            ISSUE_TILE(kt + 1, cur ^ 1);
            CP_COMMIT();
            asm volatile("cp.async.wait_group 1;" ::: "memory");
        } else {
            asm volatile("cp.async.wait_group 0;" ::: "memory");
        }
        __syncthreads();

        const float*  Kc = (const float*)(smem + OFF_K + cur * KSTAGE);
        const __half* Vc = (const __half*)(smem + OFF_V + cur * VSTAGE);
        __half* Ph = (__half*)(smem + OFF_P);

        // --- QK^T over this warp's 64-key half: t outer, 8 independent j ---
        float s[8][4];
#pragma unroll
        for (int j = 0; j < 8; j++)
            s[j][0] = s[j][1] = s[j][2] = s[j][3] = 0.0f;
#pragma unroll
        for (int t = 0; t < 8; t++) {
#pragma unroll
            for (int j = 0; j < 8; j++) {
                const uint32_t* kb = (const uint32_t*)
                    &Kc[(64 * h + 8 * j + gid) * LDK + 8 * t + tig];
                uint32_t bfr[2];
                bfr[0] = kb[0];
                bfr[1] = kb[4];
                mma_tf32(s[j], qf[t], bfr);
            }
        }

        // --- softmax (no max subtraction; logits bounded), P as fp16 ---
        {
            __half* p0 = &Ph[(16 * g + gid) * LDPH + 64 * h + 2 * tig];
            __half* p1 = p0 + 8 * LDPH;
#pragma unroll
            for (int j = 0; j < 8; j++) {
                float e0 = fast_exp2(s[j][0]);
                float e1 = fast_exp2(s[j][1]);
                float e2 = fast_exp2(s[j][2]);
                float e3 = fast_exp2(s[j][3]);
                lsum0 += e0 + e1;
                lsum1 += e2 + e3;
                *(__half2*)&p0[8 * j] = __floats2half2_rn(e0, e1);
                *(__half2*)&p1[8 * j] = __floats2half2_rn(e2, e3);
            }
        }
        __syncwarp();  // P round trip is intra-warp (own rows, own key half)

        // --- PV (fp16 m16n8k16): 4 k-groups of 16 keys, 8 d-tiles ---
        {
            const __half* pa = &Ph[(16 * g + gid) * LDPH + 64 * h + 2 * tig];
            const __half* vb = &Vc[gid * LDVH + 64 * h + 2 * tig];
#pragma unroll
            for (int t = 0; t < 4; t++) {
                uint32_t afr[4];
                afr[0] = *(const uint32_t*)&pa[16 * t];
                afr[1] = *(const uint32_t*)&pa[16 * t + 8 * LDPH];
                afr[2] = *(const uint32_t*)&pa[16 * t + 8];
                afr[3] = *(const uint32_t*)&pa[16 * t + 8 * LDPH + 8];
                const __half* vbt = vb + 16 * t;
#pragma unroll
                for (int j = 0; j < 8; j++) {
                    uint32_t bfr[2];
                    bfr[0] = *(const uint32_t*)&vbt[8 * j * LDVH];
                    bfr[1] = *(const uint32_t*)&vbt[8 * j * LDVH + 8];
                    mma_f16(o[j], afr, bfr);
                }
            }
        }
        __syncthreads();
    }
#undef ISSUE_TILE

    // --- merge warp pairs (key halves) ---
    __syncthreads();  // everyone done with P before reuse as merge buffer

    // full row sums within this warp's key half
    lsum0 += __shfl_xor_sync(0xffffffffu, lsum0, 1);
    lsum0 += __shfl_xor_sync(0xffffffffu, lsum0, 2);
    lsum1 += __shfl_xor_sync(0xffffffffu, lsum1, 1);
    lsum1 += __shfl_xor_sync(0xffffffffu, lsum1, 2);

    float* Pf = (float*)(smem + OFF_P);   // reuse P region: pair g gets 1088 floats
    float* lred = (float*)(smem + OFF_LR);

    if (h == 1) {
        float* base = &Pf[g * 1088 + gid * 68 + 2 * tig];
#pragma unroll
        for (int j = 0; j < 8; j++) {
            *(float2*)&base[8 * j] = make_float2(o[j][0], o[j][1]);
            *(float2*)&base[8 * j + 8 * 68] = make_float2(o[j][2], o[j][3]);
        }
        lred[w * 16 + gid] = lsum0;
        lred[w * 16 + 8 + gid] = lsum1;
    }
    __syncthreads();

    if (h == 0) {
        const float l0 = lsum0 + lred[(w + 1) * 16 + gid];
        const float l1 = lsum1 + lred[(w + 1) * 16 + 8 + gid];
        const float inv0 = 1.0f / l0;
        const float inv1 = 1.0f / l1;
        const float* base = &Pf[g * 1088 + gid * 68 + 2 * tig];
        float* O0 = out + ((size_t)b * SS + q0 + 16 * g + gid) * EE + 2 * tig;
        float* O1 = O0 + 8 * EE;
#pragma unroll
        for (int j = 0; j < 8; j++) {
            float2 m0 = *(const float2*)&base[8 * j];
            float2 m1 = *(const float2*)&base[8 * j + 8 * 68];
            float2 v0 = make_float2((o[j][0] + m0.x) * inv0, (o[j][1] + m0.y) * inv0);
            float2 v1 = make_float2((o[j][2] + m1.x) * inv1, (o[j][3] + m1.y) * inv1);
            *(float2*)&O0[8 * j] = v0;
            *(float2*)&O1[8 * j] = v1;
        }
    }
}

// ---------------------------------------------------------------------------

extern "C" void kernel_launch(void* const* d_in, const int* in_sizes, int n_in,
                              void* d_out, int out_size)
{
    const float* x  = (const float*)d_in[0];
    const float* Wq = (const float*)d_in[1];
    const float* bq = (const float*)d_in[2];
    const float* Wk = (const float*)d_in[3];
    const float* bk = (const float*)d_in[4];
    const float* Wv = (const float*)d_in[5];
    const float* bv = (const float*)d_in[6];
    float* out = (float*)d_out;

    cudaFuncSetAttribute(attn_mma_kernel, cudaFuncAttributeMaxDynamicSharedMemorySize,
                         (int)SMEM_ATTN);

    dim3 pgrid(BB * SS / 128, 3);
    qkv_proj_mma<<<pgrid, 256>>>(x, Wq, bq, Wk, bk, Wv, bv);

    dim3 agrid(SS / 128, BB);
    attn_mma_kernel<<<agrid, 512, SMEM_ATTN>>>(out);
}

// round 12
// speedup vs baseline: 1.2527x; 1.0092x over previous
#include <cuda_runtime.h>
#include <cuda_fp16.h>
#include <cstdint>

#define BB 4
#define SS 4096
#define WW 512
#define EE 64

// Scratch: Q,K as tf32-rounded fp32 bits (Q pre-scaled); V as fp16 TRANSPOSED [b][d][s].
__device__ float  g_Q[BB * SS * EE];
__device__ float  g_K[BB * SS * EE];
__device__ __half g_Vt[BB * EE * SS];

__device__ __forceinline__ float fast_exp2(float x) {
    float y;
    asm("ex2.approx.ftz.f32 %0, %1;" : "=f"(y) : "f"(x));
    return y;
}

__device__ __forceinline__ uint32_t f2tf(float f) {
    uint32_t r;
    asm("cvt.rna.tf32.f32 %0, %1;" : "=r"(r) : "f"(f));
    return r;
}

// D += A x B  (m16n8k8, tf32)
__device__ __forceinline__ void mma_tf32(float* d, const uint32_t* a,
                                         const uint32_t* b) {
    asm volatile(
        "mma.sync.aligned.m16n8k8.row.col.f32.tf32.tf32.f32 "
        "{%0,%1,%2,%3}, {%4,%5,%6,%7}, {%8,%9}, {%0,%1,%2,%3};"
        : "+f"(d[0]), "+f"(d[1]), "+f"(d[2]), "+f"(d[3])
        : "r"(a[0]), "r"(a[1]), "r"(a[2]), "r"(a[3]), "r"(b[0]), "r"(b[1]));
}

// D += A x B  (m16n8k16, fp16 in, fp32 accum)
__device__ __forceinline__ void mma_f16(float* d, const uint32_t* a,
                                        const uint32_t* b) {
    asm volatile(
        "mma.sync.aligned.m16n8k16.row.col.f32.f16.f16.f32 "
        "{%0,%1,%2,%3}, {%4,%5,%6,%7}, {%8,%9}, {%0,%1,%2,%3};"
        : "+f"(d[0]), "+f"(d[1]), "+f"(d[2]), "+f"(d[3])
        : "r"(a[0]), "r"(a[1]), "r"(a[2]), "r"(a[3]), "r"(b[0]), "r"(b[1]));
}

__device__ __forceinline__ uint32_t smem_u32(const void* p) {
    uint32_t a;
    asm("{ .reg .u64 t; cvta.to.shared.u64 t, %1; cvt.u32.u64 %0, t; }"
        : "=r"(a) : "l"(p));
    return a;
}

__device__ __forceinline__ void cp16(uint32_t dst, const void* src) {
    asm volatile("cp.async.cg.shared.global [%0], [%1], 16;"
                 :: "r"(dst), "l"(src));
}
#define CP_COMMIT() asm volatile("cp.async.commit_group;" ::: "memory")

#define QSCALE (0.125f * 1.4426950408889634f)

// ---------------------------------------------------------------------------
// Kernel 1: QKV projection via tf32 mma, 2-term split (x = hi + lo).
// Q/K: tf32 bits to g_Q/g_K (Q pre-scaled). V: fp16, transposed to g_Vt[d][s].
// ---------------------------------------------------------------------------
#define LDX 36
#define LDW 72

__global__ __launch_bounds__(256) void qkv_proj_mma(
    const float* __restrict__ x,
    const float* __restrict__ Wq, const float* __restrict__ bq,
    const float* __restrict__ Wk, const float* __restrict__ bk,
    const float* __restrict__ Wv, const float* __restrict__ bv)
{
    const int mat = blockIdx.y;
    const float* Wm = (mat == 0) ? Wq : (mat == 1) ? Wk : Wv;
    const float* bm = (mat == 0) ? bq : (mat == 1) ? bk : bv;

    const int row0 = blockIdx.x * 128;

    __shared__ float xh[128 * LDX];
    __shared__ float xl[128 * LDX];
    __shared__ float ws[32 * LDW];

    const int tid = threadIdx.x;
    const int w = tid >> 5;
    const int lane = tid & 31;
    const int gid = lane >> 2;
    const int tig = lane & 3;

    float o[8][4];
#pragma unroll
    for (int j = 0; j < 8; j++)
#pragma unroll
        for (int i = 0; i < 4; i++) o[j][i] = 0.0f;

    for (int k0 = 0; k0 < WW; k0 += 32) {
        __syncthreads();
#pragma unroll
        for (int it = 0; it < 4; it++) {
            int i = tid + it * 256;
            int row = i >> 3;
            int c4 = (i & 7) * 4;
            float4 v = *(const float4*)&x[(size_t)(row0 + row) * WW + k0 + c4];
            float h0 = __uint_as_float(f2tf(v.x));
            float h1 = __uint_as_float(f2tf(v.y));
            float h2 = __uint_as_float(f2tf(v.z));
            float h3 = __uint_as_float(f2tf(v.w));
            *(float4*)&xh[row * LDX + c4] = make_float4(h0, h1, h2, h3);
            float l0 = __uint_as_float(f2tf(v.x - h0));
            float l1 = __uint_as_float(f2tf(v.y - h1));
            float l2 = __uint_as_float(f2tf(v.z - h2));
            float l3 = __uint_as_float(f2tf(v.w - h3));
            *(float4*)&xl[row * LDX + c4] = make_float4(l0, l1, l2, l3);
        }
#pragma unroll
        for (int it = 0; it < 2; it++) {
            int i = tid + it * 256;
            int k = i >> 4;
            int n4 = (i & 15) * 4;
            float4 v = *(const float4*)&Wm[(size_t)(k0 + k) * EE + n4];
            *(float4*)&ws[k * LDW + n4] = make_float4(
                __uint_as_float(f2tf(v.x)), __uint_as_float(f2tf(v.y)),
                __uint_as_float(f2tf(v.z)), __uint_as_float(f2tf(v.w)));
        }
        __syncthreads();

#pragma unroll
        for (int t = 0; t < 4; t++) {
            uint32_t ah[4], al[4];
            const int base0 = (16 * w + gid) * LDX + 8 * t + tig;
            const int base1 = base0 + 8 * LDX;
            ah[0] = __float_as_uint(xh[base0]);
            ah[1] = __float_as_uint(xh[base1]);
            ah[2] = __float_as_uint(xh[base0 + 4]);
            ah[3] = __float_as_uint(xh[base1 + 4]);
            al[0] = __float_as_uint(xl[base0]);
            al[1] = __float_as_uint(xl[base1]);
            al[2] = __float_as_uint(xl[base0 + 4]);
            al[3] = __float_as_uint(xl[base1 + 4]);
#pragma unroll
            for (int j = 0; j < 8; j++) {
                const uint32_t* wb =
                    (const uint32_t*)&ws[(8 * t + tig) * LDW + 8 * j + gid];
                uint32_t bfr[2];
                bfr[0] = wb[0];
                bfr[1] = wb[4 * LDW];
                mma_tf32(o[j], ah, bfr);
                mma_tf32(o[j], al, bfr);
            }
        }
    }

    const int row = row0 + 16 * w + gid;
    if (mat == 2) {
        // V: fp16, transposed [b][d][s]
        const int bidx = row >> 12;
        const int sr = row & 4095;
#pragma unroll
        for (int j = 0; j < 8; j++) {
            int c = 8 * j + 2 * tig;
            float b0 = bm[c], b1 = bm[c + 1];
            __half* base0 = g_Vt + ((size_t)bidx * EE + c) * SS;
            __half* base1 = g_Vt + ((size_t)bidx * EE + c + 1) * SS;
            base0[sr]     = __float2half(o[j][0] + b0);
            base1[sr]     = __float2half(o[j][1] + b1);
            base0[sr + 8] = __float2half(o[j][2] + b0);
            base1[sr + 8] = __float2half(o[j][3] + b1);
        }
    } else {
        float* out = (mat == 0) ? g_Q : g_K;
        const float scale = (mat == 0) ? QSCALE : 1.0f;
#pragma unroll
        for (int j = 0; j < 8; j++) {
            int c = 8 * j + 2 * tig;
            float b0 = bm[c], b1 = bm[c + 1];
            uint2 u0 = make_uint2(f2tf((o[j][0] + b0) * scale),
                                  f2tf((o[j][1] + b1) * scale));
            *(uint2*)&out[(size_t)row * EE + c] = u0;
            uint2 u1 = make_uint2(f2tf((o[j][2] + b0) * scale),
                                  f2tf((o[j][3] + b1) * scale));
            *(uint2*)&out[(size_t)(row + 8) * EE + c] = u1;
        }
    }
}

// ---------------------------------------------------------------------------
// Kernel 2: flash attention. 512 threads (16 warps), 128 queries/CTA.
// Warp w: query group g=w>>1 (rows 16g..16g+15), key half h=w&1.
// QK: tf32 m16n8k8 over 64-key half (8 j x 8 t). PV: fp16 m16n8k16
// (4 t x 8 j). o,lsum per warp over its key half; merged at the end.
// K double-buffered f32 (stride 68), V double-buffered fp16 [d][key]
// (stride 136 halves), P fp16 (stride 136 halves). All fragment loads
// bank-conflict-free.
// ---------------------------------------------------------------------------
#define LDK 68
#define LDVH 136
#define LDPH 136
#define KSTAGE (128 * LDK * 4)          // 34816 B
#define VSTAGE (64 * LDVH * 2)          // 17408 B
#define OFF_K 0u
#define OFF_V (2u * KSTAGE)             // 69632
#define OFF_P (OFF_V + 2u * VSTAGE)     // 104448
#define OFF_LR (OFF_P + 128u * LDPH * 2u)  // 139264
#define SMEM_ATTN (OFF_LR + 1024u)      // 140288 B

__global__ __launch_bounds__(512, 1) void attn_mma_kernel(float* __restrict__ out)
{
    extern __shared__ char smem[];
    const uint32_t sb = smem_u32(smem);

    const int b = blockIdx.y;
    const int q0 = blockIdx.x * 128;
    const int tid = threadIdx.x;
    const int w = tid >> 5;
    const int g = w >> 1;
    const int h = w & 1;
    const int lane = tid & 31;
    const int gid = lane >> 2;
    const int tig = lane & 3;

    const float*  Qg = g_Q + ((size_t)b * SS + q0) * EE;
    const float*  Kg = g_K + (size_t)b * SS * EE;
    const __half* Vg = g_Vt + (size_t)b * EE * SS;

    // Q fragments (tf32 bits, pre-scaled), rows 16g+gid / +8
    uint32_t qf[8][4];
    {
        const float* Qr0 = Qg + (size_t)(16 * g + gid) * EE;
        const float* Qr1 = Qr0 + 8 * EE;
#pragma unroll
        for (int t = 0; t < 8; t++) {
            qf[t][0] = __float_as_uint(Qr0[8 * t + tig]);
            qf[t][1] = __float_as_uint(Qr1[8 * t + tig]);
            qf[t][2] = __float_as_uint(Qr0[8 * t + tig + 4]);
            qf[t][3] = __float_as_uint(Qr1[8 * t + tig + 4]);
        }
    }

    float o[8][4];
#pragma unroll
    for (int j = 0; j < 8; j++)
#pragma unroll
        for (int i = 0; i < 4; i++) o[j][i] = 0.0f;
    float lsum0 = 0.0f, lsum1 = 0.0f;

    // tile loader: K 128x64 f32 (2048 cp16), V 64x128 half (1024 cp16)
#define ISSUE_TILE(KT, S)                                                        \
    {                                                                            \
        const float* Kt = Kg + (size_t)((KT) * 128) * EE;                        \
        const uint32_t kb4 = sb + OFF_K + (uint32_t)(S) * KSTAGE;                \
        _Pragma("unroll")                                                        \
        for (int it = 0; it < 4; it++) {                                         \
            int i = tid + it * 512;                                              \
            int row = i >> 4;                                                    \
            int c4 = (i & 15) * 4;                                               \
            cp16(kb4 + (uint32_t)(row * LDK + c4) * 4u,                          \
                 Kt + (size_t)row * EE + c4);                                    \
        }                                                                        \
        const uint32_t vb2 = sb + OFF_V + (uint32_t)(S) * VSTAGE;                \
        _Pragma("unroll")                                                        \
        for (int it = 0; it < 2; it++) {                                         \
            int i = tid + it * 512;                                              \
            int row = i >> 4;                                                    \
            int c8 = (i & 15) * 8;                                               \
            cp16(vb2 + (uint32_t)(row * LDVH + c8) * 2u,                         \
                 Vg + (size_t)row * SS + (KT) * 128 + c8);                       \
        }                                                                        \
    }

    ISSUE_TILE(0, 0);
    CP_COMMIT();

    for (int kt = 0; kt < 32; kt++) {
        const int cur = kt & 1;
        if (kt < 31) {
            ISSUE_TILE(kt + 1, cur ^ 1);
            CP_COMMIT();
            asm volatile("cp.async.wait_group 1;" ::: "memory");
        } else {
            asm volatile("cp.async.wait_group 0;" ::: "memory");
        }
        __syncthreads();

        const float*  Kc = (const float*)(smem + OFF_K + cur * KSTAGE);
        const __half* Vc = (const __half*)(smem + OFF_V + cur * VSTAGE);
        __half* Ph = (__half*)(smem + OFF_P);

        // --- QK^T over this warp's 64-key half: t outer, 8 independent j ---
        float s[8][4];
#pragma unroll
        for (int j = 0; j < 8; j++)
            s[j][0] = s[j][1] = s[j][2] = s[j][3] = 0.0f;
#pragma unroll
        for (int t = 0; t < 8; t++) {
#pragma unroll
            for (int j = 0; j < 8; j++) {
                const uint32_t* kb = (const uint32_t*)
                    &Kc[(64 * h + 8 * j + gid) * LDK + 8 * t + tig];
                uint32_t bfr[2];
                bfr[0] = kb[0];
                bfr[1] = kb[4];
                mma_tf32(s[j], qf[t], bfr);
            }
        }

        // --- softmax (no max subtraction; logits bounded), P as fp16 ---
        {
            __half* p0 = &Ph[(16 * g + gid) * LDPH + 64 * h + 2 * tig];
            __half* p1 = p0 + 8 * LDPH;
#pragma unroll
            for (int j = 0; j < 8; j++) {
                float e0 = fast_exp2(s[j][0]);
                float e1 = fast_exp2(s[j][1]);
                float e2 = fast_exp2(s[j][2]);
                float e3 = fast_exp2(s[j][3]);
                lsum0 += e0 + e1;
                lsum1 += e2 + e3;
                *(__half2*)&p0[8 * j] = __floats2half2_rn(e0, e1);
                *(__half2*)&p1[8 * j] = __floats2half2_rn(e2, e3);
            }
        }
        __syncwarp();  // P round trip is intra-warp (own rows, own key half)

        // --- PV (fp16 m16n8k16): 4 k-groups of 16 keys, 8 d-tiles ---
        {
            const __half* pa = &Ph[(16 * g + gid) * LDPH + 64 * h + 2 * tig];
            const __half* vb = &Vc[gid * LDVH + 64 * h + 2 * tig];
#pragma unroll
            for (int t = 0; t < 4; t++) {
                uint32_t afr[4];
                afr[0] = *(const uint32_t*)&pa[16 * t];
                afr[1] = *(const uint32_t*)&pa[16 * t + 8 * LDPH];
                afr[2] = *(const uint32_t*)&pa[16 * t + 8];
                afr[3] = *(const uint32_t*)&pa[16 * t + 8 * LDPH + 8];
                const __half* vbt = vb + 16 * t;
#pragma unroll
                for (int j = 0; j < 8; j++) {
                    uint32_t bfr[2];
                    bfr[0] = *(const uint32_t*)&vbt[8 * j * LDVH];
                    bfr[1] = *(const uint32_t*)&vbt[8 * j * LDVH + 8];
                    mma_f16(o[j], afr, bfr);
                }
            }
        }
        __syncthreads();
    }
#undef ISSUE_TILE

    // --- merge warp pairs (key halves) ---
    __syncthreads();  // everyone done with P before reuse as merge buffer

    // full row sums within this warp's key half
    lsum0 += __shfl_xor_sync(0xffffffffu, lsum0, 1);
    lsum0 += __shfl_xor_sync(0xffffffffu, lsum0, 2);
    lsum1 += __shfl_xor_sync(0xffffffffu, lsum1, 1);
    lsum1 += __shfl_xor_sync(0xffffffffu, lsum1, 2);

    float* Pf = (float*)(smem + OFF_P);   // reuse P region: pair g gets 1088 floats
    float* lred = (float*)(smem + OFF_LR);

    if (h == 1) {
        float* base = &Pf[g * 1088 + gid * 68 + 2 * tig];
#pragma unroll
        for (int j = 0; j < 8; j++) {
            *(float2*)&base[8 * j] = make_float2(o[j][0], o[j][1]);
            *(float2*)&base[8 * j + 8 * 68] = make_float2(o[j][2], o[j][3]);
        }
        lred[w * 16 + gid] = lsum0;
        lred[w * 16 + 8 + gid] = lsum1;
    }
    __syncthreads();

    if (h == 0) {
        const float l0 = lsum0 + lred[(w + 1) * 16 + gid];
        const float l1 = lsum1 + lred[(w + 1) * 16 + 8 + gid];
        const float inv0 = 1.0f / l0;
        const float inv1 = 1.0f / l1;
        const float* base = &Pf[g * 1088 + gid * 68 + 2 * tig];
        float* O0 = out + ((size_t)b * SS + q0 + 16 * g + gid) * EE + 2 * tig;
        float* O1 = O0 + 8 * EE;
#pragma unroll
        for (int j = 0; j < 8; j++) {
            float2 m0 = *(const float2*)&base[8 * j];
            float2 m1 = *(const float2*)&base[8 * j + 8 * 68];
            float2 v0 = make_float2((o[j][0] + m0.x) * inv0, (o[j][1] + m0.y) * inv0);
            float2 v1 = make_float2((o[j][2] + m1.x) * inv1, (o[j][3] + m1.y) * inv1);
            *(float2*)&O0[8 * j] = v0;
            *(float2*)&O1[8 * j] = v1;
        }
    }
}

// ---------------------------------------------------------------------------

extern "C" void kernel_launch(void* const* d_in, const int* in_sizes, int n_in,
                              void* d_out, int out_size)
{
    const float* x  = (const float*)d_in[0];
    const float* Wq = (const float*)d_in[1];
    const float* bq = (const float*)d_in[2];
    const float* Wk = (const float*)d_in[3];
    const float* bk = (const float*)d_in[4];
    const float* Wv = (const float*)d_in[5];
    const float* bv = (const float*)d_in[6];
    float* out = (float*)d_out;

    cudaFuncSetAttribute(attn_mma_kernel, cudaFuncAttributeMaxDynamicSharedMemorySize,
                         (int)SMEM_ATTN);

    dim3 pgrid(BB * SS / 128, 3);
    qkv_proj_mma<<<pgrid, 256>>>(x, Wq, bq, Wk, bk, Wv, bv);

    dim3 agrid(SS / 128, BB);
    attn_mma_kernel<<<agrid, 512, SMEM_ATTN>>>(out);
}